// round 2
// baseline (speedup 1.0000x reference)
#include <cuda_runtime.h>
#include <cuda_bf16.h>
#include <math.h>

// Problem constants (KGramMLPSeqModel: T=1024, B=4, V=32000, E=1024, K=3, H=2048)
#define T_N   1024
#define B_N   4
#define V_N   32000
#define E_N   1024
#define KCTX  3
#define H_N   2048
#define M_N   (T_N * B_N)      // 4096 rows
#define K1_N  (KCTX * E_N)     // 3072

// Scratch for hidden activations h = silu(x @ W1 + b1): 4096 x 2048 fp32 (32 MB)
__device__ float g_h[(size_t)M_N * H_N];

// ---------------------------------------------------------------------------
// GEMM1 (gathered A) + bias + SiLU:
//   h[r, n] = silu( sum_k emb_gather(r,k) * W1[k,n] + b1[n] )
// A[r,k] = embedding[tok(r, k/E)*E + k%E], tok = tokens[t-3+slot, b] (0 if pad)
// Tiles: BM=128, BN=128, BK=16; 256 threads; 8x8 per thread.
// ---------------------------------------------------------------------------
__global__ __launch_bounds__(256)
void kgram_gemm1_silu(const int* __restrict__ tokens,
                      const float* __restrict__ emb,
                      const float* __restrict__ W1,
                      const float* __restrict__ b1,
                      float* __restrict__ Hout)
{
    __shared__ float As[16][132];   // transposed A tile, +4 pad
    __shared__ float Bs[16][132];

    const int tid = threadIdx.x;
    const int rowBase = blockIdx.y * 128;
    const int colBase = blockIdx.x * 128;
    const int ty = tid >> 4;        // 0..15
    const int tx = tid & 15;        // 0..15

    const int aRow  = tid >> 2;           // 0..63 (two steps of 64 rows)
    const int aCol4 = (tid & 3) * 4;      // 0,4,8,12
    const int bRow  = tid >> 5;           // 0..7  (two steps of 8 k-rows)
    const int bCol4 = (tid & 31) * 4;     // 0..124

    float acc[8][8];
    #pragma unroll
    for (int i = 0; i < 8; i++)
        #pragma unroll
        for (int j = 0; j < 8; j++) acc[i][j] = 0.f;

    for (int k0 = 0; k0 < K1_N; k0 += 16) {
        // --- load gathered A tile (128 rows x 16 k) ---
        #pragma unroll
        for (int s = 0; s < 2; s++) {
            const int rloc = aRow + s * 64;
            const int r = rowBase + rloc;
            const int t = r >> 2;          // row = t*B + b, B=4
            const int b = r & 3;
            const int k = k0 + aCol4;
            const int slot = k >> 10;      // k / 1024 (same for all 4 elems: k0%16==0)
            const int off  = k & 1023;
            const int tt = t - KCTX + slot;
            int tok = 0;
            if (tt >= 0) tok = tokens[tt * B_N + b];
            // clamp defensively: if token dtype assumption is wrong this avoids
            // an illegal access and surfaces as rel_err instead
            if (tok < 0) tok = 0;
            if (tok >= V_N) tok = V_N - 1;
            const float4 v = *reinterpret_cast<const float4*>(
                &emb[(size_t)tok * E_N + off]);
            As[aCol4 + 0][rloc] = v.x;
            As[aCol4 + 1][rloc] = v.y;
            As[aCol4 + 2][rloc] = v.z;
            As[aCol4 + 3][rloc] = v.w;
        }
        // --- load B tile (16 k x 128 n) from W1 ---
        #pragma unroll
        for (int s = 0; s < 2; s++) {
            const int kr = bRow + s * 8;
            const float4 v = *reinterpret_cast<const float4*>(
                &W1[(size_t)(k0 + kr) * H_N + colBase + bCol4]);
            *reinterpret_cast<float4*>(&Bs[kr][bCol4]) = v;
        }
        __syncthreads();

        #pragma unroll
        for (int kk = 0; kk < 16; kk++) {
            float a[8], b[8];
            *reinterpret_cast<float4*>(&a[0]) = *reinterpret_cast<const float4*>(&As[kk][ty * 8]);
            *reinterpret_cast<float4*>(&a[4]) = *reinterpret_cast<const float4*>(&As[kk][ty * 8 + 4]);
            *reinterpret_cast<float4*>(&b[0]) = *reinterpret_cast<const float4*>(&Bs[kk][tx * 8]);
            *reinterpret_cast<float4*>(&b[4]) = *reinterpret_cast<const float4*>(&Bs[kk][tx * 8 + 4]);
            #pragma unroll
            for (int i = 0; i < 8; i++)
                #pragma unroll
                for (int j = 0; j < 8; j++)
                    acc[i][j] = fmaf(a[i], b[j], acc[i][j]);
        }
        __syncthreads();
    }

    // epilogue: + b1, silu, store to g_h
    const int colOff = colBase + tx * 8;
    float bias[8];
    *reinterpret_cast<float4*>(&bias[0]) = *reinterpret_cast<const float4*>(&b1[colOff]);
    *reinterpret_cast<float4*>(&bias[4]) = *reinterpret_cast<const float4*>(&b1[colOff + 4]);
    #pragma unroll
    for (int i = 0; i < 8; i++) {
        const int r = rowBase + ty * 8 + i;
        float out[8];
        #pragma unroll
        for (int j = 0; j < 8; j++) {
            const float v = acc[i][j] + bias[j];
            out[j] = v / (1.f + expf(-v));   // silu
        }
        float* dst = &Hout[(size_t)r * H_N + colOff];
        *reinterpret_cast<float4*>(dst)     = *reinterpret_cast<float4*>(&out[0]);
        *reinterpret_cast<float4*>(dst + 4) = *reinterpret_cast<float4*>(&out[4]);
    }
}

// ---------------------------------------------------------------------------
// GEMM2 + bias: logits[r, n] = sum_k h[r,k] * Wout[k,n] + bout[n]
// M=4096, K=2048, N=32000. Same tiling.
// ---------------------------------------------------------------------------
__global__ __launch_bounds__(256)
void kgram_gemm2(const float* __restrict__ Hin,
                 const float* __restrict__ Wout,
                 const float* __restrict__ bout,
                 float* __restrict__ out)
{
    __shared__ float As[16][132];
    __shared__ float Bs[16][132];

    const int tid = threadIdx.x;
    const int rowBase = blockIdx.y * 128;
    const int colBase = blockIdx.x * 128;
    const int ty = tid >> 4;
    const int tx = tid & 15;

    const int aRow  = tid >> 2;
    const int aCol4 = (tid & 3) * 4;
    const int bRow  = tid >> 5;
    const int bCol4 = (tid & 31) * 4;

    float acc[8][8];
    #pragma unroll
    for (int i = 0; i < 8; i++)
        #pragma unroll
        for (int j = 0; j < 8; j++) acc[i][j] = 0.f;

    for (int k0 = 0; k0 < H_N; k0 += 16) {
        #pragma unroll
        for (int s = 0; s < 2; s++) {
            const int rloc = aRow + s * 64;
            const float4 v = *reinterpret_cast<const float4*>(
                &Hin[(size_t)(rowBase + rloc) * H_N + k0 + aCol4]);
            As[aCol4 + 0][rloc] = v.x;
            As[aCol4 + 1][rloc] = v.y;
            As[aCol4 + 2][rloc] = v.z;
            As[aCol4 + 3][rloc] = v.w;
        }
        #pragma unroll
        for (int s = 0; s < 2; s++) {
            const int kr = bRow + s * 8;
            const float4 v = *reinterpret_cast<const float4*>(
                &Wout[(size_t)(k0 + kr) * V_N + colBase + bCol4]);
            *reinterpret_cast<float4*>(&Bs[kr][bCol4]) = v;
        }
        __syncthreads();

        #pragma unroll
        for (int kk = 0; kk < 16; kk++) {
            float a[8], b[8];
            *reinterpret_cast<float4*>(&a[0]) = *reinterpret_cast<const float4*>(&As[kk][ty * 8]);
            *reinterpret_cast<float4*>(&a[4]) = *reinterpret_cast<const float4*>(&As[kk][ty * 8 + 4]);
            *reinterpret_cast<float4*>(&b[0]) = *reinterpret_cast<const float4*>(&Bs[kk][tx * 8]);
            *reinterpret_cast<float4*>(&b[4]) = *reinterpret_cast<const float4*>(&Bs[kk][tx * 8 + 4]);
            #pragma unroll
            for (int i = 0; i < 8; i++)
                #pragma unroll
                for (int j = 0; j < 8; j++)
                    acc[i][j] = fmaf(a[i], b[j], acc[i][j]);
        }
        __syncthreads();
    }

    const int colOff = colBase + tx * 8;
    float bias[8];
    *reinterpret_cast<float4*>(&bias[0]) = *reinterpret_cast<const float4*>(&bout[colOff]);
    *reinterpret_cast<float4*>(&bias[4]) = *reinterpret_cast<const float4*>(&bout[colOff + 4]);
    #pragma unroll
    for (int i = 0; i < 8; i++) {
        const int r = rowBase + ty * 8 + i;
        float o[8];
        #pragma unroll
        for (int j = 0; j < 8; j++) o[j] = acc[i][j] + bias[j];
        float* dst = &out[(size_t)r * V_N + colOff];
        *reinterpret_cast<float4*>(dst)     = *reinterpret_cast<float4*>(&o[0]);
        *reinterpret_cast<float4*>(dst + 4) = *reinterpret_cast<float4*>(&o[4]);
    }
}

// ---------------------------------------------------------------------------
// Launch
// ---------------------------------------------------------------------------
extern "C" void kernel_launch(void* const* d_in, const int* in_sizes, int n_in,
                              void* d_out, int out_size)
{
    const int*   tokens = (const int*)d_in[0];     // (T, B) int32 (JAX x64 disabled)
    const float* emb    = (const float*)d_in[1];   // (V, E)
    const float* W1     = (const float*)d_in[2];   // (K*E, H)
    const float* b1     = (const float*)d_in[3];   // (H,)
    const float* Wout   = (const float*)d_in[4];   // (H, V)
    const float* bout   = (const float*)d_in[5];   // (V,)
    float*       out    = (float*)d_out;           // (T, B, V) fp32

    float* h_scratch = nullptr;
    cudaGetSymbolAddress((void**)&h_scratch, g_h);

    dim3 block(256);
    dim3 grid1(H_N / 128, M_N / 128);   // (16, 32)
    kgram_gemm1_silu<<<grid1, block>>>(tokens, emb, W1, b1, h_scratch);

    dim3 grid2(V_N / 128, M_N / 128);   // (250, 32)
    kgram_gemm2<<<grid2, block>>>(h_scratch, Wout, bout, out);
}

// round 4
// speedup vs baseline: 1.7576x; 1.7576x over previous
#include <cuda_runtime.h>
#include <cuda_bf16.h>
#include <cstdint>
#include <math.h>

// Problem constants (KGramMLPSeqModel: T=1024, B=4, V=32000, E=1024, K=3, H=2048)
#define T_N   1024
#define B_N   4
#define V_N   32000
#define E_N   1024
#define KCTX  3
#define H_N   2048
#define M_N   (T_N * B_N)      // 4096
#define K1_N  (KCTX * E_N)     // 3072

// ---------------------------------------------------------------------------
// Device scratch (__device__ globals per allocation-free rule)
// ---------------------------------------------------------------------------
__device__ __nv_bfloat16 g_hh[(size_t)M_N * H_N];   // h hi   (M,K) K-major
__device__ __nv_bfloat16 g_hl[(size_t)M_N * H_N];   // h lo
__device__ __nv_bfloat16 g_wh[(size_t)V_N * H_N];   // Wout^T hi (N,K) K-major
__device__ __nv_bfloat16 g_wl[(size_t)V_N * H_N];   // Wout^T lo

// ---------------------------------------------------------------------------
// Helpers (baseline PTX only: works on plain compute_103 target)
// ---------------------------------------------------------------------------
__device__ __forceinline__ uint32_t smem_u32(const void* p) {
    uint32_t a;
    asm("{ .reg .u64 t; cvta.to.shared.u64 t, %1; cvt.u32.u64 %0, t; }" : "=r"(a) : "l"(p));
    return a;
}
#define CP16(dst, src) \
    asm volatile("cp.async.cg.shared.global [%0], [%1], 16;" :: "r"(dst), "l"(src) : "memory")
#define CP_COMMIT() asm volatile("cp.async.commit_group;" ::: "memory")
#define CP_WAIT1()  asm volatile("cp.async.wait_group 1;" ::: "memory")

#define LDSM4(r, addr) \
    asm volatile("ldmatrix.sync.aligned.m8n8.x4.shared.b16 {%0,%1,%2,%3}, [%4];" \
        : "=r"((r)[0]), "=r"((r)[1]), "=r"((r)[2]), "=r"((r)[3]) : "r"(addr))

#define MMA16816(d, a, b0, b1) \
    asm volatile("mma.sync.aligned.m16n8k16.row.col.f32.bf16.bf16.f32 " \
        "{%0,%1,%2,%3}, {%4,%5,%6,%7}, {%8,%9}, {%0,%1,%2,%3};" \
        : "+f"((d)[0]), "+f"((d)[1]), "+f"((d)[2]), "+f"((d)[3]) \
        : "r"((a)[0]), "r"((a)[1]), "r"((a)[2]), "r"((a)[3]), "r"(b0), "r"(b1))

__device__ __forceinline__ void split_bf16(float v, __nv_bfloat16& hi, __nv_bfloat16& lo) {
    hi = __float2bfloat16(v);
    lo = __float2bfloat16(v - __bfloat162float(hi));
}

// ---------------------------------------------------------------------------
// Prepass: Wout (H,V) fp32 -> transposed (V,H) bf16 hi/lo
// ---------------------------------------------------------------------------
__global__ __launch_bounds__(256)
void wout_split_transpose(const float* __restrict__ Wout)
{
    __shared__ float tile[32][33];
    const int tx = threadIdx.x & 31;
    const int ty = threadIdx.x >> 5;          // 0..7
    const int nBase = blockIdx.x * 32;        // V dim
    const int kBase = blockIdx.y * 32;        // H dim

    #pragma unroll
    for (int j = 0; j < 4; j++) {
        const int k = kBase + ty + j * 8;
        tile[ty + j * 8][tx] = Wout[(size_t)k * V_N + nBase + tx];
    }
    __syncthreads();
    #pragma unroll
    for (int j = 0; j < 4; j++) {
        const int n = nBase + ty + j * 8;
        const int k = kBase + tx;
        __nv_bfloat16 hi, lo;
        split_bf16(tile[tx][ty + j * 8], hi, lo);
        g_wh[(size_t)n * H_N + k] = hi;
        g_wl[(size_t)n * H_N + k] = lo;
    }
}

// ---------------------------------------------------------------------------
// GEMM1 (gathered A) + bias + SiLU -> h as bf16 hi/lo (fp32 SIMT core)
// ---------------------------------------------------------------------------
__global__ __launch_bounds__(256)
void kgram_gemm1_silu(const int* __restrict__ tokens,
                      const float* __restrict__ emb,
                      const float* __restrict__ W1,
                      const float* __restrict__ b1)
{
    __shared__ float As[16][132];
    __shared__ float Bs[16][132];

    const int tid = threadIdx.x;
    const int rowBase = blockIdx.y * 128;
    const int colBase = blockIdx.x * 128;
    const int ty = tid >> 4;
    const int tx = tid & 15;

    const int aRow  = tid >> 2;
    const int aCol4 = (tid & 3) * 4;
    const int bRow  = tid >> 5;
    const int bCol4 = (tid & 31) * 4;

    float acc[8][8];
    #pragma unroll
    for (int i = 0; i < 8; i++)
        #pragma unroll
        for (int j = 0; j < 8; j++) acc[i][j] = 0.f;

    for (int k0 = 0; k0 < K1_N; k0 += 16) {
        #pragma unroll
        for (int s = 0; s < 2; s++) {
            const int rloc = aRow + s * 64;
            const int r = rowBase + rloc;
            const int t = r >> 2;
            const int b = r & 3;
            const int k = k0 + aCol4;
            const int slot = k >> 10;
            const int off  = k & 1023;
            const int tt = t - KCTX + slot;
            int tok = 0;
            if (tt >= 0) tok = tokens[tt * B_N + b];
            if (tok < 0) tok = 0;
            if (tok >= V_N) tok = V_N - 1;
            const float4 v = *reinterpret_cast<const float4*>(&emb[(size_t)tok * E_N + off]);
            As[aCol4 + 0][rloc] = v.x;
            As[aCol4 + 1][rloc] = v.y;
            As[aCol4 + 2][rloc] = v.z;
            As[aCol4 + 3][rloc] = v.w;
        }
        #pragma unroll
        for (int s = 0; s < 2; s++) {
            const int kr = bRow + s * 8;
            const float4 v = *reinterpret_cast<const float4*>(
                &W1[(size_t)(k0 + kr) * H_N + colBase + bCol4]);
            *reinterpret_cast<float4*>(&Bs[kr][bCol4]) = v;
        }
        __syncthreads();

        #pragma unroll
        for (int kk = 0; kk < 16; kk++) {
            float a[8], b[8];
            *reinterpret_cast<float4*>(&a[0]) = *reinterpret_cast<const float4*>(&As[kk][ty * 8]);
            *reinterpret_cast<float4*>(&a[4]) = *reinterpret_cast<const float4*>(&As[kk][ty * 8 + 4]);
            *reinterpret_cast<float4*>(&b[0]) = *reinterpret_cast<const float4*>(&Bs[kk][tx * 8]);
            *reinterpret_cast<float4*>(&b[4]) = *reinterpret_cast<const float4*>(&Bs[kk][tx * 8 + 4]);
            #pragma unroll
            for (int i = 0; i < 8; i++)
                #pragma unroll
                for (int j = 0; j < 8; j++)
                    acc[i][j] = fmaf(a[i], b[j], acc[i][j]);
        }
        __syncthreads();
    }

    const int colOff = colBase + tx * 8;
    float bias[8];
    *reinterpret_cast<float4*>(&bias[0]) = *reinterpret_cast<const float4*>(&b1[colOff]);
    *reinterpret_cast<float4*>(&bias[4]) = *reinterpret_cast<const float4*>(&b1[colOff + 4]);
    #pragma unroll
    for (int i = 0; i < 8; i++) {
        const int r = rowBase + ty * 8 + i;
        #pragma unroll
        for (int j = 0; j < 8; j++) {
            const float v = acc[i][j] + bias[j];
            const float hval = v / (1.f + expf(-v));   // silu
            __nv_bfloat16 hi, lo;
            split_bf16(hval, hi, lo);
            g_hh[(size_t)r * H_N + colOff + j] = hi;
            g_hl[(size_t)r * H_N + colOff + j] = lo;
        }
    }
}

// ---------------------------------------------------------------------------
// GEMM2 via mma.sync (HMMA bf16, fp32 accum), hi/lo 3-product split.
// BM=128, BN=128, BK=32; 8 warps (2M x 4N), warp tile 64x32.
// SMEM: 2 stages x (AH|AL|BH|BL), each matrix 128 rows x 80B (64B data + 16B pad)
// cp.async double-buffered pipeline.
// ---------------------------------------------------------------------------
#define G2_BK      32
#define G2_NCHUNK  (H_N / G2_BK)    // 64
#define ROWB       80               // bytes per smem row
#define MAT_BYTES  (128 * ROWB)     // 10240
#define OFF_AH     0
#define OFF_AL     (1 * MAT_BYTES)
#define OFF_BH     (2 * MAT_BYTES)
#define OFF_BL     (3 * MAT_BYTES)
#define STAGE_B    (4 * MAT_BYTES)  // 40960
#define G2_SMEM    (2 * STAGE_B)    // 81920

__global__ __launch_bounds__(256, 1)
void kgram_gemm2_mma(const __nv_bfloat16* __restrict__ hh,
                     const __nv_bfloat16* __restrict__ hl,
                     const __nv_bfloat16* __restrict__ wh,
                     const __nv_bfloat16* __restrict__ wl,
                     const float* __restrict__ bout,
                     float* __restrict__ out)
{
    extern __shared__ char smem[];
    const uint32_t sb = smem_u32(smem);
    const int tid  = threadIdx.x;
    const int wid  = tid >> 5;
    const int lane = tid & 31;
    const int wm   = wid >> 2;          // 0..1 (M)
    const int wn   = wid & 3;           // 0..3 (N)

    const int rowBase = blockIdx.x * 128;   // M fastest -> A reuse in L2
    const int colBase = blockIdx.y * 128;   // N

    float acc[4][4][4];
    #pragma unroll
    for (int i = 0; i < 4; i++)
        #pragma unroll
        for (int j = 0; j < 4; j++)
            #pragma unroll
            for (int e = 0; e < 4; e++) acc[i][j][e] = 0.f;

    // per-thread load slots: idx = tid + it*256 -> row = idx>>2 (0..127), col16 = idx&3
    const int ldRow0 = tid >> 2;
    const int ldCol  = (tid & 3) * 16;   // byte offset within 64B row data

    auto load_stage = [&](int c, int buf) {
        const int c0 = c * G2_BK;
        const uint32_t stb = sb + buf * STAGE_B;
        #pragma unroll
        for (int it = 0; it < 2; it++) {
            const int row = ldRow0 + it * 64;
            const uint32_t d = stb + row * ROWB + ldCol;
            const size_t gA = (size_t)(rowBase + row) * H_N + c0 + (ldCol >> 1);
            const size_t gB = (size_t)(colBase + row) * H_N + c0 + (ldCol >> 1);
            CP16(d + OFF_AH, hh + gA);
            CP16(d + OFF_AL, hl + gA);
            CP16(d + OFF_BH, wh + gB);
            CP16(d + OFF_BL, wl + gB);
        }
    };

    // prologue: stages 0,1
    load_stage(0, 0); CP_COMMIT();
    load_stage(1, 1); CP_COMMIT();

    const int rsel = lane & 15;
    const int cselB = (lane >> 4) * 16;   // byte offset of k-half within row

    for (int c = 0; c < G2_NCHUNK; c++) {
        const int buf = c & 1;
        CP_WAIT1();
        __syncthreads();

        const uint32_t stb = sb + buf * STAGE_B;
        #pragma unroll
        for (int kk = 0; kk < 2; kk++) {
            const uint32_t colb = cselB + kk * 32;   // kk*16 elems *2B
            // A fragments (4 m16 tiles, hi+lo)
            uint32_t ah[4][4], al[4][4];
            #pragma unroll
            for (int im = 0; im < 4; im++) {
                const uint32_t a = stb + OFF_AH + (wm * 64 + im * 16 + rsel) * ROWB + colb;
                LDSM4(ah[im], a);
                LDSM4(al[im], a + (OFF_AL - OFF_AH));
            }
            // B fragments (2 n16 groups -> 4 n8 frags, hi+lo)
            uint32_t bh[2][4], bl[2][4];
            #pragma unroll
            for (int in = 0; in < 2; in++) {
                const uint32_t a = stb + OFF_BH + (wn * 32 + in * 16 + rsel) * ROWB + colb;
                LDSM4(bh[in], a);
                LDSM4(bl[in], a + (OFF_BL - OFF_BH));
            }
            #pragma unroll
            for (int im = 0; im < 4; im++) {
                #pragma unroll
                for (int jn = 0; jn < 4; jn++) {
                    const int g = jn >> 1, h = jn & 1;
                    MMA16816(acc[im][jn], ah[im], bh[g][h], bh[g][h + 2]);
                    MMA16816(acc[im][jn], ah[im], bl[g][h], bl[g][h + 2]);
                    MMA16816(acc[im][jn], al[im], bh[g][h], bh[g][h + 2]);
                }
            }
        }
        __syncthreads();

        if (c + 2 < G2_NCHUNK) load_stage(c + 2, buf);
        CP_COMMIT();
    }

    // Epilogue: acc -> gmem with bias
    const int mw = rowBase + wm * 64;
    const int nw = colBase + wn * 32;
    #pragma unroll
    for (int im = 0; im < 4; im++) {
        const int r0 = mw + im * 16 + (lane >> 2);
        #pragma unroll
        for (int jn = 0; jn < 4; jn++) {
            const int col = nw + jn * 8 + (lane & 3) * 2;
            const float2 bb = *reinterpret_cast<const float2*>(&bout[col]);
            float2 o0, o1;
            o0.x = acc[im][jn][0] + bb.x;
            o0.y = acc[im][jn][1] + bb.y;
            o1.x = acc[im][jn][2] + bb.x;
            o1.y = acc[im][jn][3] + bb.y;
            *reinterpret_cast<float2*>(&out[(size_t)r0 * V_N + col])       = o0;
            *reinterpret_cast<float2*>(&out[(size_t)(r0 + 8) * V_N + col]) = o1;
        }
    }
}

// ---------------------------------------------------------------------------
// Launch
// ---------------------------------------------------------------------------
extern "C" void kernel_launch(void* const* d_in, const int* in_sizes, int n_in,
                              void* d_out, int out_size)
{
    const int*   tokens = (const int*)d_in[0];     // (T, B) int32
    const float* emb    = (const float*)d_in[1];   // (V, E)
    const float* W1     = (const float*)d_in[2];   // (K*E, H)
    const float* b1     = (const float*)d_in[3];   // (H,)
    const float* Wout   = (const float*)d_in[4];   // (H, V)
    const float* bout   = (const float*)d_in[5];   // (V,)
    float*       out    = (float*)d_out;           // (T, B, V) fp32

    __nv_bfloat16 *hh, *hl, *wh, *wl;
    cudaGetSymbolAddress((void**)&hh, g_hh);
    cudaGetSymbolAddress((void**)&hl, g_hl);
    cudaGetSymbolAddress((void**)&wh, g_wh);
    cudaGetSymbolAddress((void**)&wl, g_wl);

    // Prepass: Wout transpose + bf16 split
    wout_split_transpose<<<dim3(V_N / 32, H_N / 32), 256>>>(Wout);

    // GEMM1 (fp32 SIMT) -> h bf16 hi/lo
    kgram_gemm1_silu<<<dim3(H_N / 128, M_N / 128), 256>>>(tokens, emb, W1, b1);

    // GEMM2 (mma.sync bf16 3-split)
    cudaFuncSetAttribute(kgram_gemm2_mma, cudaFuncAttributeMaxDynamicSharedMemorySize, G2_SMEM);
    kgram_gemm2_mma<<<dim3(M_N / 128, V_N / 128), 256, G2_SMEM>>>(hh, hl, wh, wl, bout, out);
}

// round 5
// speedup vs baseline: 2.0912x; 1.1898x over previous
#include <cuda_runtime.h>
#include <cuda_bf16.h>
#include <cstdint>
#include <math.h>

// Problem constants (KGramMLPSeqModel: T=1024, B=4, V=32000, E=1024, K=3, H=2048)
#define T_N   1024
#define B_N   4
#define V_N   32000
#define E_N   1024
#define KCTX  3
#define H_N   2048
#define M_N   (T_N * B_N)      // 4096
#define K1_N  (KCTX * E_N)     // 3072

// ---------------------------------------------------------------------------
// Device scratch (__device__ globals per allocation-free rule)
// ---------------------------------------------------------------------------
__device__ __nv_bfloat16 g_hh[(size_t)M_N * H_N];    // h hi   (M,H) K-major
__device__ __nv_bfloat16 g_hl[(size_t)M_N * H_N];    // h lo
__device__ __nv_bfloat16 g_wh[(size_t)V_N * H_N];    // Wout^T hi (V,H) K-major
__device__ __nv_bfloat16 g_wl[(size_t)V_N * H_N];    // Wout^T lo
__device__ __nv_bfloat16 g_eh[(size_t)V_N * E_N];    // embedding hi (V,E)
__device__ __nv_bfloat16 g_el[(size_t)V_N * E_N];    // embedding lo
__device__ __nv_bfloat16 g_w1h[(size_t)H_N * K1_N];  // W1^T hi (H,K1) K-major
__device__ __nv_bfloat16 g_w1l[(size_t)H_N * K1_N];  // W1^T lo

// ---------------------------------------------------------------------------
// Helpers (baseline PTX only: plain compute_103 target)
// ---------------------------------------------------------------------------
__device__ __forceinline__ uint32_t smem_u32(const void* p) {
    uint32_t a;
    asm("{ .reg .u64 t; cvta.to.shared.u64 t, %1; cvt.u32.u64 %0, t; }" : "=r"(a) : "l"(p));
    return a;
}
#define CP16(dst, src) \
    asm volatile("cp.async.cg.shared.global [%0], [%1], 16;" :: "r"(dst), "l"(src) : "memory")
#define CP_COMMIT() asm volatile("cp.async.commit_group;" ::: "memory")
#define CP_WAIT1()  asm volatile("cp.async.wait_group 1;" ::: "memory")

#define LDSM4(r, addr) \
    asm volatile("ldmatrix.sync.aligned.m8n8.x4.shared.b16 {%0,%1,%2,%3}, [%4];" \
        : "=r"((r)[0]), "=r"((r)[1]), "=r"((r)[2]), "=r"((r)[3]) : "r"(addr))

#define MMA16816(d, a, b0, b1) \
    asm volatile("mma.sync.aligned.m16n8k16.row.col.f32.bf16.bf16.f32 " \
        "{%0,%1,%2,%3}, {%4,%5,%6,%7}, {%8,%9}, {%0,%1,%2,%3};" \
        : "+f"((d)[0]), "+f"((d)[1]), "+f"((d)[2]), "+f"((d)[3]) \
        : "r"((a)[0]), "r"((a)[1]), "r"((a)[2]), "r"((a)[3]), "r"(b0), "r"(b1))

__device__ __forceinline__ void split_bf16(float v, __nv_bfloat16& hi, __nv_bfloat16& lo) {
    hi = __float2bfloat16(v);
    lo = __float2bfloat16(v - __bfloat162float(hi));
}

// ---------------------------------------------------------------------------
// Prepass A: elementwise split (embedding): fp32 -> bf16 hi/lo, same layout
// ---------------------------------------------------------------------------
__global__ __launch_bounds__(256)
void emb_split(const float* __restrict__ emb)
{
    const size_t i4 = ((size_t)blockIdx.x * 256 + threadIdx.x) * 4;
    const float4 v = *reinterpret_cast<const float4*>(emb + i4);
    __nv_bfloat16 h0, l0, h1, l1, h2, l2, h3, l3;
    split_bf16(v.x, h0, l0); split_bf16(v.y, h1, l1);
    split_bf16(v.z, h2, l2); split_bf16(v.w, h3, l3);
    __nv_bfloat162* oh = reinterpret_cast<__nv_bfloat162*>(g_eh + i4);
    __nv_bfloat162* ol = reinterpret_cast<__nv_bfloat162*>(g_el + i4);
    oh[0] = __nv_bfloat162(h0, h1); oh[1] = __nv_bfloat162(h2, h3);
    ol[0] = __nv_bfloat162(l0, l1); ol[1] = __nv_bfloat162(l2, l3);
}

// ---------------------------------------------------------------------------
// Prepass B: transpose + split: in (R, C) fp32 -> out (C, R) bf16 hi/lo
// ---------------------------------------------------------------------------
__global__ __launch_bounds__(256)
void split_transpose(const float* __restrict__ in,
                     __nv_bfloat16* __restrict__ oh,
                     __nv_bfloat16* __restrict__ ol,
                     int R, int C)
{
    __shared__ float tile[32][33];
    const int tx = threadIdx.x & 31;
    const int ty = threadIdx.x >> 5;          // 0..7
    const int cBase = blockIdx.x * 32;
    const int rBase = blockIdx.y * 32;

    #pragma unroll
    for (int j = 0; j < 4; j++)
        tile[ty + j * 8][tx] = in[(size_t)(rBase + ty + j * 8) * C + cBase + tx];
    __syncthreads();
    #pragma unroll
    for (int j = 0; j < 4; j++) {
        const int n = cBase + ty + j * 8;
        const int k = rBase + tx;
        __nv_bfloat16 hi, lo;
        split_bf16(tile[tx][ty + j * 8], hi, lo);
        oh[(size_t)n * R + k] = hi;
        ol[(size_t)n * R + k] = lo;
    }
}

// ---------------------------------------------------------------------------
// Shared GEMM geometry: ROWB=80 (64B data + 16B pad) -> conflict-free ldmatrix
// ---------------------------------------------------------------------------
#define ROWB 80

// ============================================================================
// GEMM1 via mma.sync: h = silu(gather(emb) @ W1 + b1), output bf16 hi/lo.
// BM=128, BN=128, BK=32; 8 warps (2Mx4N), warp tile 64x32. 96 chunks.
// ============================================================================
#define G1_NCHUNK  (K1_N / 32)      // 96
#define MAT1       (128 * ROWB)     // 10240
#define O1_AH      0
#define O1_AL      (1 * MAT1)
#define O1_BH      (2 * MAT1)
#define O1_BL      (3 * MAT1)
#define STAGE1     (4 * MAT1)       // 40960
#define G1_SMEM    (2 * STAGE1)     // 81920

__global__ __launch_bounds__(256, 1)
void kgram_gemm1_mma(const int* __restrict__ tokens,
                     const __nv_bfloat16* __restrict__ eh,
                     const __nv_bfloat16* __restrict__ el,
                     const __nv_bfloat16* __restrict__ w1h,
                     const __nv_bfloat16* __restrict__ w1l,
                     const float* __restrict__ b1)
{
    extern __shared__ char smem[];
    const uint32_t sb = smem_u32(smem);
    const int tid  = threadIdx.x;
    const int wid  = tid >> 5;
    const int lane = tid & 31;
    const int wm   = wid >> 2;          // 0..1
    const int wn   = wid & 3;           // 0..3

    const int rowBase = blockIdx.x * 128;
    const int colBase = blockIdx.y * 128;

    float acc[4][4][4];
    #pragma unroll
    for (int i = 0; i < 4; i++)
        #pragma unroll
        for (int j = 0; j < 4; j++)
            #pragma unroll
            for (int e = 0; e < 4; e++) acc[i][j][e] = 0.f;

    const int ldRow0 = tid >> 2;
    const int ldSeg  = tid & 3;
    const int ldCol  = ldSeg * 16;

    auto load_stage = [&](int c, int buf) {
        const int c0 = c * 32;
        const uint32_t stb = sb + buf * STAGE1;
        const int kidx = c0 + ldSeg * 8;
        const int slot = kidx >> 10;
        const int off  = kidx & 1023;
        #pragma unroll
        for (int it = 0; it < 2; it++) {
            const int row = ldRow0 + it * 64;
            const int r = rowBase + row;
            const int t = r >> 2;
            const int b = r & 3;
            const int tt = t - KCTX + slot;
            int tok = 0;
            if (tt >= 0) tok = tokens[tt * B_N + b];
            if (tok < 0) tok = 0;
            if (tok >= V_N) tok = V_N - 1;
            const size_t gA = (size_t)tok * E_N + off;
            const uint32_t d = stb + row * ROWB + ldCol;
            CP16(d + O1_AH, eh + gA);
            CP16(d + O1_AL, el + gA);
            const size_t gB = (size_t)(colBase + row) * K1_N + c0 + ldSeg * 8;
            CP16(d + O1_BH, w1h + gB);
            CP16(d + O1_BL, w1l + gB);
        }
    };

    load_stage(0, 0); CP_COMMIT();
    load_stage(1, 1); CP_COMMIT();

    const int rsel  = lane & 15;
    const int cselB = (lane >> 4) * 16;

    for (int c = 0; c < G1_NCHUNK; c++) {
        const int buf = c & 1;
        CP_WAIT1();
        __syncthreads();

        const uint32_t stb = sb + buf * STAGE1;
        #pragma unroll
        for (int kk = 0; kk < 2; kk++) {
            const uint32_t colb = cselB + kk * 32;
            uint32_t ah[4][4], al[4][4];
            #pragma unroll
            for (int im = 0; im < 4; im++) {
                const uint32_t a = stb + O1_AH + (wm * 64 + im * 16 + rsel) * ROWB + colb;
                LDSM4(ah[im], a);
                LDSM4(al[im], a + (O1_AL - O1_AH));
            }
            uint32_t bh[2][4], bl[2][4];
            #pragma unroll
            for (int in = 0; in < 2; in++) {
                const uint32_t a = stb + O1_BH + (wn * 32 + in * 16 + rsel) * ROWB + colb;
                LDSM4(bh[in], a);
                LDSM4(bl[in], a + (O1_BL - O1_BH));
            }
            #pragma unroll
            for (int im = 0; im < 4; im++) {
                #pragma unroll
                for (int jn = 0; jn < 4; jn++) {
                    const int g = jn >> 1, h = jn & 1;
                    MMA16816(acc[im][jn], ah[im], bh[g][h], bh[g][h + 2]);
                    MMA16816(acc[im][jn], ah[im], bl[g][h], bl[g][h + 2]);
                    MMA16816(acc[im][jn], al[im], bh[g][h], bh[g][h + 2]);
                }
            }
        }
        __syncthreads();

        if (c + 2 < G1_NCHUNK) load_stage(c + 2, buf);
        CP_COMMIT();
    }

    // Epilogue: +b1, silu, split -> g_hh/g_hl
    const int mw = rowBase + wm * 64;
    const int nw = colBase + wn * 32;
    #pragma unroll
    for (int im = 0; im < 4; im++) {
        const int r0 = mw + im * 16 + (lane >> 2);
        #pragma unroll
        for (int jn = 0; jn < 4; jn++) {
            const int col = nw + jn * 8 + (lane & 3) * 2;
            const float2 bb = *reinterpret_cast<const float2*>(&b1[col]);
            float v00 = acc[im][jn][0] + bb.x;
            float v01 = acc[im][jn][1] + bb.y;
            float v10 = acc[im][jn][2] + bb.x;
            float v11 = acc[im][jn][3] + bb.y;
            v00 = v00 / (1.f + expf(-v00));
            v01 = v01 / (1.f + expf(-v01));
            v10 = v10 / (1.f + expf(-v10));
            v11 = v11 / (1.f + expf(-v11));
            __nv_bfloat16 h00, l00, h01, l01, h10, l10, h11, l11;
            split_bf16(v00, h00, l00); split_bf16(v01, h01, l01);
            split_bf16(v10, h10, l10); split_bf16(v11, h11, l11);
            *reinterpret_cast<__nv_bfloat162*>(g_hh + (size_t)r0 * H_N + col) =
                __nv_bfloat162(h00, h01);
            *reinterpret_cast<__nv_bfloat162*>(g_hl + (size_t)r0 * H_N + col) =
                __nv_bfloat162(l00, l01);
            *reinterpret_cast<__nv_bfloat162*>(g_hh + (size_t)(r0 + 8) * H_N + col) =
                __nv_bfloat162(h10, h11);
            *reinterpret_cast<__nv_bfloat162*>(g_hl + (size_t)(r0 + 8) * H_N + col) =
                __nv_bfloat162(l10, l11);
        }
    }
}

// ============================================================================
// GEMM2 via mma.sync: logits = h @ Wout + bout.
// BM=128, BN=256, BK=32; 8 warps (2Mx4N), warp tile 64x64. 64 chunks.
// ============================================================================
#define G2_NCHUNK  (H_N / 32)       // 64
#define A2_BYTES   (128 * ROWB)     // 10240
#define B2_BYTES   (256 * ROWB)     // 20480
#define O2_AH      0
#define O2_AL      A2_BYTES
#define O2_BH      (2 * A2_BYTES)
#define O2_BL      (2 * A2_BYTES + B2_BYTES)
#define STAGE2     (2 * A2_BYTES + 2 * B2_BYTES)   // 61440
#define G2_SMEM    (2 * STAGE2)                    // 122880

__global__ __launch_bounds__(256, 1)
void kgram_gemm2_mma(const __nv_bfloat16* __restrict__ hh,
                     const __nv_bfloat16* __restrict__ hl,
                     const __nv_bfloat16* __restrict__ wh,
                     const __nv_bfloat16* __restrict__ wl,
                     const float* __restrict__ bout,
                     float* __restrict__ out)
{
    extern __shared__ char smem[];
    const uint32_t sb = smem_u32(smem);
    const int tid  = threadIdx.x;
    const int wid  = tid >> 5;
    const int lane = tid & 31;
    const int wm   = wid >> 2;          // 0..1 (M)
    const int wn   = wid & 3;           // 0..3 (N) -> 64 cols each

    const int rowBase = blockIdx.x * 128;   // M fastest -> A reuse in L2
    const int colBase = blockIdx.y * 256;   // N

    float acc[4][8][4];
    #pragma unroll
    for (int i = 0; i < 4; i++)
        #pragma unroll
        for (int j = 0; j < 8; j++)
            #pragma unroll
            for (int e = 0; e < 4; e++) acc[i][j][e] = 0.f;

    const int ldRow0 = tid >> 2;
    const int ldCol  = (tid & 3) * 16;

    auto load_stage = [&](int c, int buf) {
        const int c0 = c * 32;
        const uint32_t stb = sb + buf * STAGE2;
        // A: 128 rows (hi+lo)
        #pragma unroll
        for (int it = 0; it < 2; it++) {
            const int row = ldRow0 + it * 64;
            const uint32_t d = stb + row * ROWB + ldCol;
            const size_t gA = (size_t)(rowBase + row) * H_N + c0 + (ldCol >> 1);
            CP16(d + O2_AH, hh + gA);
            CP16(d + O2_AL, hl + gA);
        }
        // B: 256 rows (hi+lo)
        #pragma unroll
        for (int it = 0; it < 4; it++) {
            const int row = ldRow0 + it * 64;
            const uint32_t d = stb + row * ROWB + ldCol;
            const size_t gB = (size_t)(colBase + row) * H_N + c0 + (ldCol >> 1);
            CP16(d + O2_BH, wh + gB);
            CP16(d + O2_BL, wl + gB);
        }
    };

    load_stage(0, 0); CP_COMMIT();
    load_stage(1, 1); CP_COMMIT();

    const int rsel  = lane & 15;
    const int cselB = (lane >> 4) * 16;

    for (int c = 0; c < G2_NCHUNK; c++) {
        const int buf = c & 1;
        CP_WAIT1();
        __syncthreads();

        const uint32_t stb = sb + buf * STAGE2;
        #pragma unroll
        for (int kk = 0; kk < 2; kk++) {
            const uint32_t colb = cselB + kk * 32;
            uint32_t ah[4][4], al[4][4];
            #pragma unroll
            for (int im = 0; im < 4; im++) {
                const uint32_t a = stb + O2_AH + (wm * 64 + im * 16 + rsel) * ROWB + colb;
                LDSM4(ah[im], a);
                LDSM4(al[im], a + (O2_AL - O2_AH));
            }
            uint32_t bh[4][4], bl[4][4];
            #pragma unroll
            for (int in = 0; in < 4; in++) {
                const uint32_t a = stb + O2_BH + (wn * 64 + in * 16 + rsel) * ROWB + colb;
                LDSM4(bh[in], a);
                LDSM4(bl[in], a + (O2_BL - O2_BH));
            }
            #pragma unroll
            for (int im = 0; im < 4; im++) {
                #pragma unroll
                for (int jn = 0; jn < 8; jn++) {
                    const int g = jn >> 1, h = jn & 1;
                    MMA16816(acc[im][jn], ah[im], bh[g][h], bh[g][h + 2]);
                    MMA16816(acc[im][jn], ah[im], bl[g][h], bl[g][h + 2]);
                    MMA16816(acc[im][jn], al[im], bh[g][h], bh[g][h + 2]);
                }
            }
        }
        __syncthreads();

        if (c + 2 < G2_NCHUNK) load_stage(c + 2, buf);
        CP_COMMIT();
    }

    // Epilogue: +bout -> gmem
    const int mw = rowBase + wm * 64;
    const int nw = colBase + wn * 64;
    #pragma unroll
    for (int im = 0; im < 4; im++) {
        const int r0 = mw + im * 16 + (lane >> 2);
        #pragma unroll
        for (int jn = 0; jn < 8; jn++) {
            const int col = nw + jn * 8 + (lane & 3) * 2;
            const float2 bb = *reinterpret_cast<const float2*>(&bout[col]);
            float2 o0, o1;
            o0.x = acc[im][jn][0] + bb.x;
            o0.y = acc[im][jn][1] + bb.y;
            o1.x = acc[im][jn][2] + bb.x;
            o1.y = acc[im][jn][3] + bb.y;
            *reinterpret_cast<float2*>(&out[(size_t)r0 * V_N + col])       = o0;
            *reinterpret_cast<float2*>(&out[(size_t)(r0 + 8) * V_N + col]) = o1;
        }
    }
}

// ---------------------------------------------------------------------------
// Launch
// ---------------------------------------------------------------------------
extern "C" void kernel_launch(void* const* d_in, const int* in_sizes, int n_in,
                              void* d_out, int out_size)
{
    const int*   tokens = (const int*)d_in[0];     // (T, B) int32
    const float* emb    = (const float*)d_in[1];   // (V, E)
    const float* W1     = (const float*)d_in[2];   // (K*E, H)
    const float* b1     = (const float*)d_in[3];   // (H,)
    const float* Wout   = (const float*)d_in[4];   // (H, V)
    const float* bout   = (const float*)d_in[5];   // (V,)
    float*       out    = (float*)d_out;           // (T, B, V) fp32

    __nv_bfloat16 *hh, *hl, *wh, *wl, *eh, *el, *w1h, *w1l;
    cudaGetSymbolAddress((void**)&hh, g_hh);
    cudaGetSymbolAddress((void**)&hl, g_hl);
    cudaGetSymbolAddress((void**)&wh, g_wh);
    cudaGetSymbolAddress((void**)&wl, g_wl);
    cudaGetSymbolAddress((void**)&eh, g_eh);
    cudaGetSymbolAddress((void**)&el, g_el);
    cudaGetSymbolAddress((void**)&w1h, g_w1h);
    cudaGetSymbolAddress((void**)&w1l, g_w1l);

    // Prepasses
    emb_split<<<(int)(((size_t)V_N * E_N) / 1024), 256>>>(emb);
    split_transpose<<<dim3(H_N / 32, K1_N / 32), 256>>>(W1, w1h, w1l, K1_N, H_N);
    split_transpose<<<dim3(V_N / 32, H_N / 32), 256>>>(Wout, wh, wl, H_N, V_N);

    // GEMM1 (HMMA bf16 3-split, gathered A) -> h bf16 hi/lo
    cudaFuncSetAttribute(kgram_gemm1_mma, cudaFuncAttributeMaxDynamicSharedMemorySize, G1_SMEM);
    kgram_gemm1_mma<<<dim3(M_N / 128, H_N / 128), 256, G1_SMEM>>>(tokens, eh, el, w1h, w1l, b1);

    // GEMM2 (HMMA bf16 3-split)
    cudaFuncSetAttribute(kgram_gemm2_mma, cudaFuncAttributeMaxDynamicSharedMemorySize, G2_SMEM);
    kgram_gemm2_mma<<<dim3(M_N / 128, V_N / 256), 256, G2_SMEM>>>(hh, hl, wh, wl, bout, out);
}

// round 6
// speedup vs baseline: 2.1073x; 1.0077x over previous
#include <cuda_runtime.h>
#include <cuda_bf16.h>
#include <cstdint>
#include <math.h>

// Problem constants (KGramMLPSeqModel: T=1024, B=4, V=32000, E=1024, K=3, H=2048)
#define T_N   1024
#define B_N   4
#define V_N   32000
#define E_N   1024
#define KCTX  3
#define H_N   2048
#define M_N   (T_N * B_N)      // 4096
#define K1_N  (KCTX * E_N)     // 3072

// ---------------------------------------------------------------------------
// Device scratch (__device__ globals per allocation-free rule)
// ---------------------------------------------------------------------------
__device__ __nv_bfloat16 g_hh[(size_t)M_N * H_N];    // h hi   (M,H) K-major
__device__ __nv_bfloat16 g_hl[(size_t)M_N * H_N];    // h lo
__device__ __nv_bfloat16 g_wh[(size_t)V_N * H_N];    // Wout^T hi (V,H) K-major
__device__ __nv_bfloat16 g_wl[(size_t)V_N * H_N];    // Wout^T lo
__device__ __nv_bfloat16 g_eh[(size_t)V_N * E_N];    // embedding hi (V,E)
__device__ __nv_bfloat16 g_el[(size_t)V_N * E_N];    // embedding lo
__device__ __nv_bfloat16 g_w1h[(size_t)H_N * K1_N];  // W1^T hi (H,K1) K-major
__device__ __nv_bfloat16 g_w1l[(size_t)H_N * K1_N];  // W1^T lo

// ---------------------------------------------------------------------------
// Helpers (baseline PTX only: plain compute_103 target)
// ---------------------------------------------------------------------------
__device__ __forceinline__ uint32_t smem_u32(const void* p) {
    uint32_t a;
    asm("{ .reg .u64 t; cvta.to.shared.u64 t, %1; cvt.u32.u64 %0, t; }" : "=r"(a) : "l"(p));
    return a;
}
#define CP16(dst, src) \
    asm volatile("cp.async.cg.shared.global [%0], [%1], 16;" :: "r"(dst), "l"(src) : "memory")
#define CP_COMMIT() asm volatile("cp.async.commit_group;" ::: "memory")
#define CP_WAIT1()  asm volatile("cp.async.wait_group 1;" ::: "memory")

#define LDSM4(r, addr) \
    asm volatile("ldmatrix.sync.aligned.m8n8.x4.shared.b16 {%0,%1,%2,%3}, [%4];" \
        : "=r"((r)[0]), "=r"((r)[1]), "=r"((r)[2]), "=r"((r)[3]) : "r"(addr))

#define MMA16816(d, a, b0, b1) \
    asm volatile("mma.sync.aligned.m16n8k16.row.col.f32.bf16.bf16.f32 " \
        "{%0,%1,%2,%3}, {%4,%5,%6,%7}, {%8,%9}, {%0,%1,%2,%3};" \
        : "+f"((d)[0]), "+f"((d)[1]), "+f"((d)[2]), "+f"((d)[3]) \
        : "r"((a)[0]), "r"((a)[1]), "r"((a)[2]), "r"((a)[3]), "r"(b0), "r"(b1))

__device__ __forceinline__ void split_bf16(float v, __nv_bfloat16& hi, __nv_bfloat16& lo) {
    hi = __float2bfloat16(v);
    lo = __float2bfloat16(v - __bfloat162float(hi));
}

// ---------------------------------------------------------------------------
// Prepass A: elementwise split (embedding): fp32 -> bf16 hi/lo, same layout
// ---------------------------------------------------------------------------
__global__ __launch_bounds__(256)
void emb_split(const float* __restrict__ emb)
{
    const size_t i4 = ((size_t)blockIdx.x * 256 + threadIdx.x) * 4;
    const float4 v = *reinterpret_cast<const float4*>(emb + i4);
    __nv_bfloat16 h0, l0, h1, l1, h2, l2, h3, l3;
    split_bf16(v.x, h0, l0); split_bf16(v.y, h1, l1);
    split_bf16(v.z, h2, l2); split_bf16(v.w, h3, l3);
    __nv_bfloat162* oh = reinterpret_cast<__nv_bfloat162*>(g_eh + i4);
    __nv_bfloat162* ol = reinterpret_cast<__nv_bfloat162*>(g_el + i4);
    oh[0] = __nv_bfloat162(h0, h1); oh[1] = __nv_bfloat162(h2, h3);
    ol[0] = __nv_bfloat162(l0, l1); ol[1] = __nv_bfloat162(l2, l3);
}

// ---------------------------------------------------------------------------
// Prepass B: transpose + split: in (R, C) fp32 -> out (C, R) bf16 hi/lo
// ---------------------------------------------------------------------------
__global__ __launch_bounds__(256)
void split_transpose(const float* __restrict__ in,
                     __nv_bfloat16* __restrict__ oh,
                     __nv_bfloat16* __restrict__ ol,
                     int R, int C)
{
    __shared__ float tile[32][33];
    const int tx = threadIdx.x & 31;
    const int ty = threadIdx.x >> 5;          // 0..7
    const int cBase = blockIdx.x * 32;
    const int rBase = blockIdx.y * 32;

    #pragma unroll
    for (int j = 0; j < 4; j++)
        tile[ty + j * 8][tx] = in[(size_t)(rBase + ty + j * 8) * C + cBase + tx];
    __syncthreads();
    #pragma unroll
    for (int j = 0; j < 4; j++) {
        const int n = cBase + ty + j * 8;
        const int k = rBase + tx;
        __nv_bfloat16 hi, lo;
        split_bf16(tile[tx][ty + j * 8], hi, lo);
        oh[(size_t)n * R + k] = hi;
        ol[(size_t)n * R + k] = lo;
    }
}

// ---------------------------------------------------------------------------
// Shared GEMM geometry (both GEMMs):
//   BM=128, BN=256, BK=32; 8 warps (2M x 4N), warp tile 64x64.
//   ROWB=80 (64B data + 16B pad) -> conflict-free ldmatrix phases.
//   3-stage cp.async pipeline, loads issued before compute.
// ---------------------------------------------------------------------------
#define ROWB      80
#define A_BYTES   (128 * ROWB)     // 10240
#define B_BYTES   (256 * ROWB)     // 20480
#define OFF_AH    0
#define OFF_AL    A_BYTES
#define OFF_BH    (2 * A_BYTES)
#define OFF_BL    (2 * A_BYTES + B_BYTES)
#define STAGE_B   (2 * A_BYTES + 2 * B_BYTES)   // 61440
#define NSTAGE    3
#define GEMM_SMEM (NSTAGE * STAGE_B)            // 184320

// Compute one 32-k chunk for warp tile 64x64 (acc[4][8][4]); 3-product split.
#define COMPUTE_CHUNK(stb)                                                          \
    do {                                                                            \
        _Pragma("unroll")                                                           \
        for (int kk = 0; kk < 2; kk++) {                                            \
            const uint32_t colb = cselB + kk * 32;                                  \
            uint32_t ah[4][4], al[4][4];                                            \
            _Pragma("unroll")                                                       \
            for (int im = 0; im < 4; im++) {                                        \
                const uint32_t a = (stb) + OFF_AH + (wm * 64 + im * 16 + rsel) * ROWB + colb; \
                LDSM4(ah[im], a);                                                   \
                LDSM4(al[im], a + (OFF_AL - OFF_AH));                               \
            }                                                                       \
            uint32_t bh[4][4], bl[4][4];                                            \
            _Pragma("unroll")                                                       \
            for (int in = 0; in < 4; in++) {                                        \
                const uint32_t a = (stb) + OFF_BH + (wn * 64 + in * 16 + rsel) * ROWB + colb; \
                LDSM4(bh[in], a);                                                   \
                LDSM4(bl[in], a + (OFF_BL - OFF_BH));                               \
            }                                                                       \
            _Pragma("unroll")                                                       \
            for (int im = 0; im < 4; im++) {                                        \
                _Pragma("unroll")                                                   \
                for (int jn = 0; jn < 8; jn++) {                                    \
                    const int g = jn >> 1, h = jn & 1;                              \
                    MMA16816(acc[im][jn], ah[im], bh[g][h], bh[g][h + 2]);          \
                    MMA16816(acc[im][jn], ah[im], bl[g][h], bl[g][h + 2]);          \
                    MMA16816(acc[im][jn], al[im], bh[g][h], bh[g][h + 2]);          \
                }                                                                   \
            }                                                                       \
        }                                                                           \
    } while (0)

// ============================================================================
// GEMM1: h = silu(gather(emb) @ W1 + b1) -> bf16 hi/lo.  96 chunks.
// ============================================================================
#define G1_NCHUNK (K1_N / 32)   // 96

__global__ __launch_bounds__(256, 1)
void kgram_gemm1_mma(const int* __restrict__ tokens,
                     const __nv_bfloat16* __restrict__ eh,
                     const __nv_bfloat16* __restrict__ el,
                     const __nv_bfloat16* __restrict__ w1h,
                     const __nv_bfloat16* __restrict__ w1l,
                     const float* __restrict__ b1)
{
    extern __shared__ char smem[];
    const uint32_t sb = smem_u32(smem);
    const int tid  = threadIdx.x;
    const int wid  = tid >> 5;
    const int lane = tid & 31;
    const int wm   = wid >> 2;
    const int wn   = wid & 3;

    const int rowBase = blockIdx.x * 128;
    const int colBase = blockIdx.y * 256;

    float acc[4][8][4];
    #pragma unroll
    for (int i = 0; i < 4; i++)
        #pragma unroll
        for (int j = 0; j < 8; j++)
            #pragma unroll
            for (int e = 0; e < 4; e++) acc[i][j][e] = 0.f;

    const int ldRow0 = tid >> 2;
    const int ldSeg  = tid & 3;
    const int ldCol  = ldSeg * 16;

    auto load_stage = [&](int c) {
        const int c0 = c * 32;
        const uint32_t stb = sb + (c % NSTAGE) * STAGE_B;
        const int kidx = c0 + ldSeg * 8;
        const int slot = kidx >> 10;
        const int off  = kidx & 1023;
        // A: gathered embedding rows (128 rows, hi+lo)
        #pragma unroll
        for (int it = 0; it < 2; it++) {
            const int row = ldRow0 + it * 64;
            const int r = rowBase + row;
            const int t = r >> 2;
            const int b = r & 3;
            const int tt = t - KCTX + slot;
            int tok = 0;
            if (tt >= 0) tok = tokens[tt * B_N + b];
            if (tok < 0) tok = 0;
            if (tok >= V_N) tok = V_N - 1;
            const size_t gA = (size_t)tok * E_N + off;
            const uint32_t d = stb + row * ROWB + ldCol;
            CP16(d + OFF_AH, eh + gA);
            CP16(d + OFF_AL, el + gA);
        }
        // B: W1^T (256 rows, hi+lo)
        #pragma unroll
        for (int it = 0; it < 4; it++) {
            const int row = ldRow0 + it * 64;
            const uint32_t d = stb + row * ROWB + ldCol;
            const size_t gB = (size_t)(colBase + row) * K1_N + c0 + ldSeg * 8;
            CP16(d + OFF_BH, w1h + gB);
            CP16(d + OFF_BL, w1l + gB);
        }
    };

    load_stage(0); CP_COMMIT();
    load_stage(1); CP_COMMIT();

    const int rsel  = lane & 15;
    const int cselB = (lane >> 4) * 16;

    for (int c = 0; c < G1_NCHUNK; c++) {
        CP_WAIT1();
        __syncthreads();
        if (c + 2 < G1_NCHUNK) load_stage(c + 2);
        CP_COMMIT();
        const uint32_t stb = sb + (c % NSTAGE) * STAGE_B;
        COMPUTE_CHUNK(stb);
    }

    // Epilogue: +b1, silu, split -> g_hh/g_hl
    const int mw = rowBase + wm * 64;
    const int nw = colBase + wn * 64;
    #pragma unroll
    for (int im = 0; im < 4; im++) {
        const int r0 = mw + im * 16 + (lane >> 2);
        #pragma unroll
        for (int jn = 0; jn < 8; jn++) {
            const int col = nw + jn * 8 + (lane & 3) * 2;
            const float2 bb = *reinterpret_cast<const float2*>(&b1[col]);
            float v00 = acc[im][jn][0] + bb.x;
            float v01 = acc[im][jn][1] + bb.y;
            float v10 = acc[im][jn][2] + bb.x;
            float v11 = acc[im][jn][3] + bb.y;
            v00 = v00 / (1.f + expf(-v00));
            v01 = v01 / (1.f + expf(-v01));
            v10 = v10 / (1.f + expf(-v10));
            v11 = v11 / (1.f + expf(-v11));
            __nv_bfloat16 h00, l00, h01, l01, h10, l10, h11, l11;
            split_bf16(v00, h00, l00); split_bf16(v01, h01, l01);
            split_bf16(v10, h10, l10); split_bf16(v11, h11, l11);
            *reinterpret_cast<__nv_bfloat162*>(g_hh + (size_t)r0 * H_N + col) =
                __nv_bfloat162(h00, h01);
            *reinterpret_cast<__nv_bfloat162*>(g_hl + (size_t)r0 * H_N + col) =
                __nv_bfloat162(l00, l01);
            *reinterpret_cast<__nv_bfloat162*>(g_hh + (size_t)(r0 + 8) * H_N + col) =
                __nv_bfloat162(h10, h11);
            *reinterpret_cast<__nv_bfloat162*>(g_hl + (size_t)(r0 + 8) * H_N + col) =
                __nv_bfloat162(l10, l11);
        }
    }
}

// ============================================================================
// GEMM2: logits = h @ Wout + bout.  64 chunks.
// ============================================================================
#define G2_NCHUNK (H_N / 32)    // 64

__global__ __launch_bounds__(256, 1)
void kgram_gemm2_mma(const __nv_bfloat16* __restrict__ hh,
                     const __nv_bfloat16* __restrict__ hl,
                     const __nv_bfloat16* __restrict__ wh,
                     const __nv_bfloat16* __restrict__ wl,
                     const float* __restrict__ bout,
                     float* __restrict__ out)
{
    extern __shared__ char smem[];
    const uint32_t sb = smem_u32(smem);
    const int tid  = threadIdx.x;
    const int wid  = tid >> 5;
    const int lane = tid & 31;
    const int wm   = wid >> 2;
    const int wn   = wid & 3;

    const int rowBase = blockIdx.x * 128;   // M fastest -> B-strip reuse in L2
    const int colBase = blockIdx.y * 256;

    float acc[4][8][4];
    #pragma unroll
    for (int i = 0; i < 4; i++)
        #pragma unroll
        for (int j = 0; j < 8; j++)
            #pragma unroll
            for (int e = 0; e < 4; e++) acc[i][j][e] = 0.f;

    const int ldRow0 = tid >> 2;
    const int ldCol  = (tid & 3) * 16;

    auto load_stage = [&](int c) {
        const int c0 = c * 32;
        const uint32_t stb = sb + (c % NSTAGE) * STAGE_B;
        #pragma unroll
        for (int it = 0; it < 2; it++) {
            const int row = ldRow0 + it * 64;
            const uint32_t d = stb + row * ROWB + ldCol;
            const size_t gA = (size_t)(rowBase + row) * H_N + c0 + (ldCol >> 1);
            CP16(d + OFF_AH, hh + gA);
            CP16(d + OFF_AL, hl + gA);
        }
        #pragma unroll
        for (int it = 0; it < 4; it++) {
            const int row = ldRow0 + it * 64;
            const uint32_t d = stb + row * ROWB + ldCol;
            const size_t gB = (size_t)(colBase + row) * H_N + c0 + (ldCol >> 1);
            CP16(d + OFF_BH, wh + gB);
            CP16(d + OFF_BL, wl + gB);
        }
    };

    load_stage(0); CP_COMMIT();
    load_stage(1); CP_COMMIT();

    const int rsel  = lane & 15;
    const int cselB = (lane >> 4) * 16;

    for (int c = 0; c < G2_NCHUNK; c++) {
        CP_WAIT1();
        __syncthreads();
        if (c + 2 < G2_NCHUNK) load_stage(c + 2);
        CP_COMMIT();
        const uint32_t stb = sb + (c % NSTAGE) * STAGE_B;
        COMPUTE_CHUNK(stb);
    }

    // Epilogue: +bout -> gmem
    const int mw = rowBase + wm * 64;
    const int nw = colBase + wn * 64;
    #pragma unroll
    for (int im = 0; im < 4; im++) {
        const int r0 = mw + im * 16 + (lane >> 2);
        #pragma unroll
        for (int jn = 0; jn < 8; jn++) {
            const int col = nw + jn * 8 + (lane & 3) * 2;
            const float2 bb = *reinterpret_cast<const float2*>(&bout[col]);
            float2 o0, o1;
            o0.x = acc[im][jn][0] + bb.x;
            o0.y = acc[im][jn][1] + bb.y;
            o1.x = acc[im][jn][2] + bb.x;
            o1.y = acc[im][jn][3] + bb.y;
            *reinterpret_cast<float2*>(&out[(size_t)r0 * V_N + col])       = o0;
            *reinterpret_cast<float2*>(&out[(size_t)(r0 + 8) * V_N + col]) = o1;
        }
    }
}

// ---------------------------------------------------------------------------
// Launch
// ---------------------------------------------------------------------------
extern "C" void kernel_launch(void* const* d_in, const int* in_sizes, int n_in,
                              void* d_out, int out_size)
{
    const int*   tokens = (const int*)d_in[0];     // (T, B) int32
    const float* emb    = (const float*)d_in[1];   // (V, E)
    const float* W1     = (const float*)d_in[2];   // (K*E, H)
    const float* b1     = (const float*)d_in[3];   // (H,)
    const float* Wout   = (const float*)d_in[4];   // (H, V)
    const float* bout   = (const float*)d_in[5];   // (V,)
    float*       out    = (float*)d_out;           // (T, B, V) fp32

    __nv_bfloat16 *hh, *hl, *wh, *wl, *eh, *el, *w1h, *w1l;
    cudaGetSymbolAddress((void**)&hh, g_hh);
    cudaGetSymbolAddress((void**)&hl, g_hl);
    cudaGetSymbolAddress((void**)&wh, g_wh);
    cudaGetSymbolAddress((void**)&wl, g_wl);
    cudaGetSymbolAddress((void**)&eh, g_eh);
    cudaGetSymbolAddress((void**)&el, g_el);
    cudaGetSymbolAddress((void**)&w1h, g_w1h);
    cudaGetSymbolAddress((void**)&w1l, g_w1l);

    // Prepasses
    emb_split<<<(int)(((size_t)V_N * E_N) / 1024), 256>>>(emb);
    split_transpose<<<dim3(H_N / 32, K1_N / 32), 256>>>(W1, w1h, w1l, K1_N, H_N);
    split_transpose<<<dim3(V_N / 32, H_N / 32), 256>>>(Wout, wh, wl, H_N, V_N);

    // GEMM1 (HMMA bf16 3-split, gathered A) -> h bf16 hi/lo
    cudaFuncSetAttribute(kgram_gemm1_mma, cudaFuncAttributeMaxDynamicSharedMemorySize, GEMM_SMEM);
    kgram_gemm1_mma<<<dim3(M_N / 128, H_N / 256), 256, GEMM_SMEM>>>(tokens, eh, el, w1h, w1l, b1);

    // GEMM2 (HMMA bf16 3-split)
    cudaFuncSetAttribute(kgram_gemm2_mma, cudaFuncAttributeMaxDynamicSharedMemorySize, GEMM_SMEM);
    kgram_gemm2_mma<<<dim3(M_N / 128, V_N / 256), 256, GEMM_SMEM>>>(hh, hl, wh, wl, bout, out);
}